// round 17
// baseline (speedup 1.0000x reference)
#include <cuda_runtime.h>
#include <cooperative_groups.h>
#include <cstdint>

namespace cg = cooperative_groups;

// Problem dims
#define Bv 32
#define Cv 1024
#define Nv 784
#define Mv 4
#define N4v 196      // Nv/4
#define GR 8         // rows per generation
#define GEN 8        // generations per block
#define BROWS 64     // GR*GEN rows per block
#define CHUNKS 16    // Cv/BROWS
#define GSZ (GR * N4v)   // 1568 float4 per generation buffer

// Scratch (device globals)
__device__ float  g_invnorm[Bv][Cv];
__device__ float4 g_tpart[Bv][CHUNKS][Mv][N4v];  // per-chunk partials (6.4 MB)
__device__ float4 g_h[Bv][N4v];                  // h[b,n] = sum_m g/s

__device__ __forceinline__ void cp_async16(uint32_t saddr, const void* gaddr) {
    asm volatile("cp.async.cg.shared.global [%0], [%1], 16;\n" :: "r"(saddr), "l"(gaddr));
}
__device__ __forceinline__ void cp_commit() {
    asm volatile("cp.async.commit_group;\n");
}
template <int N>
__device__ __forceinline__ void cp_wait() {
    asm volatile("cp.async.wait_group %0;\n" :: "n"(N));
}

extern __shared__ float4 smem_dyn[];  // 2 * GSZ float4 = 50176 B

// ---------------------------------------------------------------------------
// Fused cooperative kernel: phase1 = proven kAB pipeline; grid.sync;
// phase2 = kC on blocks 0..31; grid.sync; phase3 = kD (8 rows/warp,
// 4-row interleave). One launch, no inter-kernel gaps.
// ---------------------------------------------------------------------------
__global__ void __launch_bounds__(256, 4) kFused(const float* __restrict__ x,
                                                 const float* __restrict__ Wm,
                                                 float* __restrict__ out) {
    cg::grid_group grid = cg::this_grid();
    __shared__ float4 swsc[GR];
    int bid = blockIdx.x;
    int b = bid >> 4, ch = bid & 15;
    int p0 = ch * BROWS;
    int t = threadIdx.x;
    int warp = t >> 5, lane = t & 31;
    const float4* base = reinterpret_cast<const float4*>(x) + ((size_t)b * Cv + p0) * N4v;
    uint32_t sbase = (uint32_t)__cvta_generic_to_shared(smem_dyn);

    // ======================= Phase 1: norms + t-partials =======================
#pragma unroll
    for (int k = 0; k < 7; ++k) {
        int i = t + k * 256;
        if (i < GSZ) cp_async16(sbase + i * 16u, base + i);
    }
    cp_commit();

    float4 a0 = {0, 0, 0, 0}, a1 = a0, a2 = a0, a3 = a0;

#pragma unroll
    for (int g = 0; g < GEN; ++g) {
        if (g + 1 < GEN) {
            uint32_t sb = sbase + ((g + 1) & 1) * (GSZ * 16u);
            const float4* gb = base + (g + 1) * GSZ;
#pragma unroll
            for (int k = 0; k < 7; ++k) {
                int i = t + k * 256;
                if (i < GSZ) cp_async16(sb + i * 16u, gb + i);
            }
            cp_commit();
            cp_wait<1>();
        } else {
            cp_wait<0>();
        }
        __syncthreads();

        float4* cur = smem_dyn + (g & 1) * GSZ;

        // norms: warp w handles row w
        {
            float s = 0.f;
#pragma unroll
            for (int k = 0; k < 7; ++k) {
                int idx = lane + k * 32;
                if (idx < N4v) {
                    float4 v = cur[warp * N4v + idx];
                    s += v.x * v.x + v.y * v.y + v.z * v.z + v.w * v.w;
                }
            }
#pragma unroll
            for (int o = 16; o; o >>= 1) s += __shfl_xor_sync(0xffffffffu, s, o);
            if (lane == 0) {
                float inv = 1.0f / fmaxf(sqrtf(s), 1e-10f);
                int p = p0 + g * GR + warp;
                g_invnorm[b][p] = inv;
                float4 w;
                w.x = Wm[0 * Cv + p] * inv;
                w.y = Wm[1 * Cv + p] * inv;
                w.z = Wm[2 * Cv + p] * inv;
                w.w = Wm[3 * Cv + p] * inv;
                swsc[warp] = w;
            }
        }
        __syncthreads();

        if (t < N4v) {
#pragma unroll
            for (int r = 0; r < GR; ++r) {
                float4 w  = swsc[r];
                float4 xv = cur[r * N4v + t];
                a0.x = fmaf(w.x, xv.x, a0.x); a0.y = fmaf(w.x, xv.y, a0.y);
                a0.z = fmaf(w.x, xv.z, a0.z); a0.w = fmaf(w.x, xv.w, a0.w);
                a1.x = fmaf(w.y, xv.x, a1.x); a1.y = fmaf(w.y, xv.y, a1.y);
                a1.z = fmaf(w.y, xv.z, a1.z); a1.w = fmaf(w.y, xv.w, a1.w);
                a2.x = fmaf(w.z, xv.x, a2.x); a2.y = fmaf(w.z, xv.y, a2.y);
                a2.z = fmaf(w.z, xv.z, a2.z); a2.w = fmaf(w.z, xv.w, a2.w);
                a3.x = fmaf(w.w, xv.x, a3.x); a3.y = fmaf(w.w, xv.y, a3.y);
                a3.z = fmaf(w.w, xv.z, a3.z); a3.w = fmaf(w.w, xv.w, a3.w);
            }
        }
        __syncthreads();
    }

    if (t < N4v) {
        g_tpart[b][ch][0][t] = a0;
        g_tpart[b][ch][1][t] = a1;
        g_tpart[b][ch][2][t] = a2;
        g_tpart[b][ch][3][t] = a3;
    }

    grid.sync();

    // ======================= Phase 2: kC on blocks 0..31 =======================
    if (bid < Bv) {
        int bb = bid;
        __shared__ float sm[Mv];
        if (t < Mv) sm[t] = 0.f;
        __syncthreads();
        float4 gg[Mv];
        float ssm[Mv];
        bool valid = (t < N4v);
#pragma unroll
        for (int m = 0; m < Mv; ++m) {
            float4 acc = {0, 0, 0, 0};
            if (valid) {
#pragma unroll
                for (int c = 0; c < CHUNKS; ++c) {
                    float4 v = g_tpart[bb][c][m][t];
                    acc.x += v.x; acc.y += v.y; acc.z += v.z; acc.w += v.w;
                }
            }
            float4 g4;
            g4.x = 1.f / (1.f + __expf(-acc.x));
            g4.y = 1.f / (1.f + __expf(-acc.y));
            g4.z = 1.f / (1.f + __expf(-acc.z));
            g4.w = 1.f / (1.f + __expf(-acc.w));
            if (!valid) g4 = make_float4(0.f, 0.f, 0.f, 0.f);
            gg[m] = g4;
            ssm[m] = g4.x * g4.x + g4.y * g4.y + g4.z * g4.z + g4.w * g4.w;
        }
#pragma unroll
        for (int o = 16; o; o >>= 1) {
            ssm[0] += __shfl_xor_sync(0xffffffffu, ssm[0], o);
            ssm[1] += __shfl_xor_sync(0xffffffffu, ssm[1], o);
            ssm[2] += __shfl_xor_sync(0xffffffffu, ssm[2], o);
            ssm[3] += __shfl_xor_sync(0xffffffffu, ssm[3], o);
        }
        if (lane == 0) {
            atomicAdd(&sm[0], ssm[0]);
            atomicAdd(&sm[1], ssm[1]);
            atomicAdd(&sm[2], ssm[2]);
            atomicAdd(&sm[3], ssm[3]);
        }
        __syncthreads();
        if (valid) {
            float i0 = 1.f / sm[0], i1 = 1.f / sm[1], i2 = 1.f / sm[2], i3 = 1.f / sm[3];
            float4 h;
            h.x = gg[0].x * i0 + gg[1].x * i1 + gg[2].x * i2 + gg[3].x * i3;
            h.y = gg[0].y * i0 + gg[1].y * i1 + gg[2].y * i2 + gg[3].y * i3;
            h.z = gg[0].z * i0 + gg[1].z * i1 + gg[2].z * i2 + gg[3].z * i3;
            h.w = gg[0].w * i0 + gg[1].w * i1 + gg[2].w * i2 + gg[3].w * i3;
            g_h[bb][t] = h;
        }
    }

    grid.sync();

    // ======================= Phase 3: kD, 8 rows/warp =======================
    {
        const float4* hb = &g_h[b][0];
#pragma unroll
        for (int j = 0; j < 2; ++j) {
            int p = p0 + warp * 8 + j * 4;   // 4 interleaved rows
            const float4* r0 = reinterpret_cast<const float4*>(x) + ((size_t)b * Cv + p) * N4v;
            const float4* r1 = r0 + N4v;
            const float4* r2 = r1 + N4v;
            const float4* r3 = r2 + N4v;
            float s0 = 0.f, s1 = 0.f, s2 = 0.f, s3 = 0.f;
#pragma unroll
            for (int k = 0; k < 6; ++k) {
                int idx = lane + k * 32;
                float4 hv = __ldg(hb + idx);
                float4 v0 = r0[idx], v1 = r1[idx], v2 = r2[idx], v3 = r3[idx];
                s0 += v0.x * hv.x + v0.y * hv.y + v0.z * hv.z + v0.w * hv.w;
                s1 += v1.x * hv.x + v1.y * hv.y + v1.z * hv.z + v1.w * hv.w;
                s2 += v2.x * hv.x + v2.y * hv.y + v2.z * hv.z + v2.w * hv.w;
                s3 += v3.x * hv.x + v3.y * hv.y + v3.z * hv.z + v3.w * hv.w;
            }
            if (lane < 4) {
                int idx = 192 + lane;
                float4 hv = __ldg(hb + idx);
                float4 v0 = r0[idx], v1 = r1[idx], v2 = r2[idx], v3 = r3[idx];
                s0 += v0.x * hv.x + v0.y * hv.y + v0.z * hv.z + v0.w * hv.w;
                s1 += v1.x * hv.x + v1.y * hv.y + v1.z * hv.z + v1.w * hv.w;
                s2 += v2.x * hv.x + v2.y * hv.y + v2.z * hv.z + v2.w * hv.w;
                s3 += v3.x * hv.x + v3.y * hv.y + v3.z * hv.z + v3.w * hv.w;
            }
#pragma unroll
            for (int o = 16; o; o >>= 1) {
                s0 += __shfl_xor_sync(0xffffffffu, s0, o);
                s1 += __shfl_xor_sync(0xffffffffu, s1, o);
                s2 += __shfl_xor_sync(0xffffffffu, s2, o);
                s3 += __shfl_xor_sync(0xffffffffu, s3, o);
            }
            if (lane == 0) {
                out[b * Cv + p]     = s0 * g_invnorm[b][p];
                out[b * Cv + p + 1] = s1 * g_invnorm[b][p + 1];
                out[b * Cv + p + 2] = s2 * g_invnorm[b][p + 2];
                out[b * Cv + p + 3] = s3 * g_invnorm[b][p + 3];
            }
        }
    }
}

extern "C" void kernel_launch(void* const* d_in, const int* in_sizes, int n_in,
                              void* d_out, int out_size) {
    const float* x  = (const float*)d_in[0];   // [32,1024,28,28] f32
    const float* Wm = (const float*)d_in[1];   // [4,1,1024] f32
    float* out = (float*)d_out;                // [32,1024] f32

    static const int smem_bytes = 2 * GSZ * sizeof(float4);  // 50176
    cudaFuncSetAttribute(kFused, cudaFuncAttributeMaxDynamicSharedMemorySize, smem_bytes);

    void* args[] = {(void*)&x, (void*)&Wm, (void*)&out};
    cudaLaunchCooperativeKernel((void*)kFused, dim3(512), dim3(256),
                                args, smem_bytes, (cudaStream_t)0);
}